// round 5
// baseline (speedup 1.0000x reference)
#include <cuda_runtime.h>

#define RES 1024
#define NUM_ROOMS 8
#define N_AGENTS 5000000
#define PLANE (RES * RES)
#define FINAL_BLOCKS 1024   // must all be co-resident: 1024 <= 148 SM * 8 blk/SM

// Scratch (no device allocation allowed)
__device__ __align__(16) float g_ex[NUM_ROOMS * RES];
__device__ __align__(16) float g_ey[NUM_ROOMS * RES];
__device__ int g_maxbits;
__device__ unsigned int g_arrived;

// ---------------------------------------------------------------------------
// Kernel 1: zero flow (float4) + build Gaussian tables + reset max/counter.
// ---------------------------------------------------------------------------
__global__ void k_init(const float* __restrict__ rooms, float4* __restrict__ flow4) {
    int tid = blockIdx.x * blockDim.x + threadIdx.x;
    if (tid < PLANE / 4) flow4[tid] = make_float4(0.f, 0.f, 0.f, 0.f);
    if (tid < NUM_ROOMS * RES) {
        int r = tid >> 10, i = tid & (RES - 1);
        float lin = (float)i * (1.0f / (RES - 1));
        float cx = rooms[r * 4 + 0], sx = rooms[r * 4 + 2];
        float cy = rooms[r * 4 + 1], sy = rooms[r * 4 + 3];
        float dx = lin - cx, dy = lin - cy;
        g_ex[tid] = __expf(-dx * dx / (2.0f * sx * sx));
        g_ey[tid] = __expf(-dy * dy / (2.0f * sy * sy));
    }
    if (tid == 0) { g_maxbits = 0; g_arrived = 0u; }
}

// ---------------------------------------------------------------------------
// Kernel 2: histogram. float4 load = 2 agents/thread, scattered RED.ADD.F32.
// At the REDG spread-lane floor (~23us); runs alone so atomics own the LTS.
// ---------------------------------------------------------------------------
__global__ void k_hist(const float4* __restrict__ pos4, float* __restrict__ flow, int npairs) {
    int tid = blockIdx.x * blockDim.x + threadIdx.x;
    if (tid >= npairs) return;
    float4 p = pos4[tid];
    int ix0 = min(max((int)(p.x * (float)RES), 0), RES - 1);
    int iy0 = min(max((int)(p.y * (float)RES), 0), RES - 1);
    int ix1 = min(max((int)(p.z * (float)RES), 0), RES - 1);
    int iy1 = min(max((int)(p.w * (float)RES), 0), RES - 1);
    atomicAdd(&flow[(ix0 << 10) | iy0], 1.0f);
    atomicAdd(&flow[(ix1 << 10) | iy1], 1.0f);
}

// ---------------------------------------------------------------------------
// Kernel 3 (fused): phase A = grid max of flow; device grid barrier;
// phase B = write 8 layout planes + normalized flow.
// Single wave: 1024 blocks x 256 thr, forced 8 blocks/SM residency.
// ---------------------------------------------------------------------------
__global__ void __launch_bounds__(256, 8)
k_final(const float4* __restrict__ wall4, float* __restrict__ out) {
    __shared__ float smax[8];
    float4* out4 = (float4*)out;
    float4* flow4 = out4 + NUM_ROOMS * (PLANE / 4);

    int tid = blockIdx.x * blockDim.x + threadIdx.x;   // 0 .. PLANE/4-1
    int lane = threadIdx.x & 31, warp = threadIdx.x >> 5;

    // ---- phase A: max reduce over flow (1 float4 per thread) ----
    float4 f = flow4[tid];
    float m = fmaxf(fmaxf(f.x, f.y), fmaxf(f.z, f.w));
    #pragma unroll
    for (int off = 16; off > 0; off >>= 1)
        m = fmaxf(m, __shfl_xor_sync(0xffffffffu, m, off));
    if (lane == 0) smax[warp] = m;
    __syncthreads();
    if (threadIdx.x == 0) {
        float bm = smax[0];
        #pragma unroll
        for (int w = 1; w < 8; w++) bm = fmaxf(bm, smax[w]);
        atomicMax(&g_maxbits, __float_as_int(bm));
        __threadfence();
        atomicAdd(&g_arrived, 1u);
        // spin until every block has contributed its max
        while (atomicAdd(&g_arrived, 0u) < (unsigned)gridDim.x) { __nanosleep(64); }
    }
    __syncthreads();   // releases whole block once thread 0 sees the barrier

    // ---- phase B: normalize flow + write 8 layout planes ----
    float inv = 1.0f / (__int_as_float(g_maxbits) + 1e-6f);
    float4 fn;
    fn.x = f.x * inv; fn.y = f.y * inv; fn.z = f.z * inv; fn.w = f.w * inv;
    flow4[tid] = fn;

    int i = tid >> 8;             // row
    int q = tid & 255;            // float4 column
    float4 w = wall4[tid];
    w.x = 1.0f - w.x; w.y = 1.0f - w.y; w.z = 1.0f - w.z; w.w = 1.0f - w.w;

    const float4* ey4 = (const float4*)g_ey;
    #pragma unroll
    for (int r = 0; r < NUM_ROOMS; r++) {
        float ex = g_ex[(r << 10) + i];
        float4 e = ey4[(r << 8) + q];
        float4 o;
        o.x = ex * e.x * w.x;
        o.y = ex * e.y * w.y;
        o.z = ex * e.z * w.z;
        o.w = ex * e.w * w.w;
        out4[r * (PLANE / 4) + tid] = o;
    }
}

// ---------------------------------------------------------------------------
extern "C" void kernel_launch(void* const* d_in, const int* in_sizes, int n_in,
                              void* d_out, int out_size) {
    const float* pos   = (const float*)d_in[0];   // [5000000, 2]
    const float* rooms = (const float*)d_in[1];   // [8, 4]
    const float* wall  = (const float*)d_in[2];   // [1024, 1024]
    float* out = (float*)d_out;                   // 8 planes + flow plane
    float* flow = out + NUM_ROOMS * PLANE;

    // 1) zero flow + build tables + reset barrier state
    k_init<<<(PLANE / 4 + 255) / 256, 256>>>(rooms, (float4*)flow);

    // 2) histogram (alone; at REDG lane floor)
    int npairs = N_AGENTS / 2;
    k_hist<<<(npairs + 255) / 256, 256>>>((const float4*)pos, flow, npairs);

    // 3) fused max + grid barrier + normalize + layout
    k_final<<<FINAL_BLOCKS, 256>>>((const float4*)wall, out);
}